// round 6
// baseline (speedup 1.0000x reference)
#include <cuda_runtime.h>
#include <cuda_fp16.h>
#include <cstdint>

// ---------------- problem constants ----------------
#define N_NODES 8192
#define DFEAT   128
#define EPS     1e-6f

// ---------------- GEMM tiling ----------------
#define BM       64
#define KSTAGE   64
#define NSTAGES  (N_NODES / KSTAGE)     // 128
#define ROWB     144                    // smem row stride bytes (64 fp16 = 128B + 16 pad)
#define ATILE    (BM * ROWB)            // 9216
#define BTILE    (DFEAT * ROWB)         // 18432
#define BUFB     (ATILE + BTILE)        // 27648
#define SMEM_DYN (2 * BUFB)             // 55296

// ---------------- scratch (no allocation allowed) ----------------
__device__ float                   g_dinv[N_NODES];
__device__ __align__(16) __half    g_zT[DFEAT * N_NODES];   // [c][k] fp16

// ---------------- helpers ----------------
static __device__ __forceinline__ uint32_t smem_u32(const void* p) {
    uint32_t a;
    asm("{ .reg .u64 t; cvta.to.shared.u64 t, %1; cvt.u32.u64 %0, t; }" : "=r"(a) : "l"(p));
    return a;
}

#define LDSM4(r, addr) \
    asm volatile("ldmatrix.sync.aligned.m8n8.x4.shared.b16 {%0,%1,%2,%3}, [%4];" \
        : "=r"((r)[0]), "=r"((r)[1]), "=r"((r)[2]), "=r"((r)[3]) : "r"(addr))

// f16-accumulate MMA: D(f16x2 x2) = A*B + C
#define MMAH(dv, a, b0, b1) \
    asm volatile("mma.sync.aligned.m16n8k16.row.col.f16.f16.f16.f16 " \
        "{%0,%1}, {%2,%3,%4,%5}, {%6,%7}, {%0,%1};" \
        : "+r"((dv)[0]), "+r"((dv)[1]) \
        : "r"((a)[0]), "r"((a)[1]), "r"((a)[2]), "r"((a)[3]), "r"(b0), "r"(b1))

static __device__ __forceinline__ uint2 f4_to_h4(float4 v) {
    __half2 p0 = __float22half2_rn(make_float2(v.x, v.y));
    __half2 p1 = __float22half2_rn(make_float2(v.z, v.w));
    uint2 r;
    r.x = *reinterpret_cast<uint32_t*>(&p0);
    r.y = *reinterpret_cast<uint32_t*>(&p1);
    return r;
}

// ---------------------------------------------------------------------------
// Kernel 1: dinv[i] = rsqrt(rowsum(adj_i) + eps)
// ---------------------------------------------------------------------------
__global__ void rowsum_kernel(const float* __restrict__ adj, float* __restrict__ dinv) {
    int row = blockIdx.x;
    const float4* p = reinterpret_cast<const float4*>(adj + (size_t)row * N_NODES);
    float s = 0.f;
    for (int j = threadIdx.x; j < N_NODES / 4; j += 256) {
        float4 v = p[j];
        s += (v.x + v.y) + (v.z + v.w);
    }
    #pragma unroll
    for (int off = 16; off > 0; off >>= 1) s += __shfl_down_sync(0xffffffffu, s, off);
    __shared__ float ws[8];
    int lane = threadIdx.x & 31, wid = threadIdx.x >> 5;
    if (lane == 0) ws[wid] = s;
    __syncthreads();
    if (wid == 0) {
        float t = (lane < 8) ? ws[lane] : 0.f;
        #pragma unroll
        for (int off = 4; off > 0; off >>= 1) t += __shfl_down_sync(0xffffffffu, t, off);
        if (lane == 0) dinv[row] = rsqrtf(t + EPS);
    }
}

// ---------------------------------------------------------------------------
// Kernel 2: zT[c][k] = fp16( dinv[k] * dot(x[k,:], W[c,:]) )   (fp32 math)
// ---------------------------------------------------------------------------
__global__ __launch_bounds__(256) void xw_kernel(
    const float* __restrict__ x, const float* __restrict__ W, const float* __restrict__ dinv,
    __half* __restrict__ zT)
{
    __shared__ float xs[8][DFEAT];
    __shared__ float zs[DFEAT][8];
    int r0 = blockIdx.x * 8;
    int t = threadIdx.x;
    for (int i = t; i < 8 * DFEAT; i += 256)
        xs[i >> 7][i & 127] = x[(size_t)r0 * DFEAT + i];
    __syncthreads();

    int c = t & 127, rh = t >> 7;
    const float4* wr = reinterpret_cast<const float4*>(W + (size_t)c * DFEAT);
    float acc[4] = {0.f, 0.f, 0.f, 0.f};
    #pragma unroll 8
    for (int k4 = 0; k4 < DFEAT / 4; k4++) {
        float4 wv = __ldg(&wr[k4]);
        #pragma unroll
        for (int j = 0; j < 4; j++) {
            const float* xr = &xs[rh * 4 + j][k4 * 4];
            acc[j] += wv.x * xr[0] + wv.y * xr[1] + wv.z * xr[2] + wv.w * xr[3];
        }
    }
    #pragma unroll
    for (int j = 0; j < 4; j++)
        zs[c][rh * 4 + j] = acc[j] * dinv[r0 + rh * 4 + j];
    __syncthreads();

    if (t < 128) {
        uint2 h0 = f4_to_h4(make_float4(zs[t][0], zs[t][1], zs[t][2], zs[t][3]));
        uint2 h1 = f4_to_h4(make_float4(zs[t][4], zs[t][5], zs[t][6], zs[t][7]));
        *reinterpret_cast<uint4*>(zT + (size_t)t * N_NODES + r0) = make_uint4(h0.x, h0.y, h1.x, h1.y);
    }
}

// ---------------------------------------------------------------------------
// Kernel 3: fp16 GEMM via mma.sync, f16 stage-accumulation, fused epilogue.
// out[m][c] = dinv[m] * sum_k adj[m][k]*z[k][c] + bias[c]
// Grid: 128 CTAs (BM=64, full K per CTA). 256 threads = 8 warps,
// warp grid 2(m) x 4(n), warp tile 32m x 32n. Double-buffered smem, KSTAGE=64.
// ---------------------------------------------------------------------------
__global__ __launch_bounds__(256, 1) void gcn_mma_kernel(
    const float* __restrict__ adj,
    const __half* __restrict__ zT,
    const float* __restrict__ dinv,
    const float* __restrict__ bias,
    float* __restrict__ out)
{
    extern __shared__ char smem[];
    const uint32_t sbase = smem_u32(smem);

    const int tid  = threadIdx.x;
    const int lane = tid & 31;
    const int wid  = tid >> 5;
    const int wm   = wid >> 2;          // 0..1
    const int wn   = wid & 3;           // 0..3

    const int m0 = blockIdx.x * BM;

    // ---- global load mapping (fully coalesced) ----
    // A: 64 rows x 64 floats = 1024 float4; 4 per thread. row = tid>>4 + i*16
    const float* aBase = adj + (size_t)(m0 + (tid >> 4)) * N_NODES + ((tid & 15) << 2);
    const uint32_t aSoff = (uint32_t)((tid >> 4) * ROWB + (tid & 15) * 8);
    // B: 128 n-rows x 64 halves = 1024 uint4; 4 per thread. n = tid>>3 + i*32
    const __half* bBase = zT + (size_t)(tid >> 3) * N_NODES + ((tid & 7) << 3);
    const uint32_t bSoff = (uint32_t)((tid >> 3) * ROWB + (tid & 7) * 16);

    // ---- ldmatrix address precompute ----
    const int idx = lane >> 3;   // 0..3
    const uint32_t a_lm = (uint32_t)((wm * 32 + (idx & 1) * 8 + (lane & 7)) * ROWB + ((idx >> 1) * 8) * 2);
    const uint32_t b_lm = (uint32_t)((wn * 32 + (idx >> 1) * 8 + (lane & 7)) * ROWB + ((idx & 1) * 8) * 2);

    float d[2][4][4];
    #pragma unroll
    for (int i = 0; i < 2; i++)
        #pragma unroll
        for (int j = 0; j < 4; j++)
            #pragma unroll
            for (int q = 0; q < 4; q++) d[i][j][q] = 0.f;

    // prefetch stage 0
    float4 aP[4];
    uint4  bP[4];
    #pragma unroll
    for (int i = 0; i < 4; i++)
        aP[i] = *reinterpret_cast<const float4*>(aBase + (size_t)(i * 16) * N_NODES);
    #pragma unroll
    for (int i = 0; i < 4; i++)
        bP[i] = *reinterpret_cast<const uint4*>(bBase + (size_t)(i * 32) * N_NODES);

    for (int s = 0; s < NSTAGES; s++) {
        const uint32_t bufb = (uint32_t)((s & 1) * BUFB);
        char* cbuf = smem + bufb;

        // ---- stage regs -> smem (fp32 -> fp16 for A) ----
        #pragma unroll
        for (int i = 0; i < 4; i++)
            *reinterpret_cast<uint2*>(cbuf + aSoff + i * (16 * ROWB)) = f4_to_h4(aP[i]);
        #pragma unroll
        for (int i = 0; i < 4; i++)
            *reinterpret_cast<uint4*>(cbuf + ATILE + bSoff + i * (32 * ROWB)) = bP[i];
        __syncthreads();

        // ---- prefetch next stage ----
        if (s + 1 < NSTAGES) {
            const int ko = (s + 1) * KSTAGE;
            #pragma unroll
            for (int i = 0; i < 4; i++)
                aP[i] = *reinterpret_cast<const float4*>(aBase + (size_t)(i * 16) * N_NODES + ko);
            #pragma unroll
            for (int i = 0; i < 4; i++)
                bP[i] = *reinterpret_cast<const uint4*>(bBase + (size_t)(i * 32) * N_NODES + ko);
        }

        // ---- MMA over this buffer: f16 accumulation within stage ----
        uint32_t hacc[2][4][2];
        #pragma unroll
        for (int mf = 0; mf < 2; mf++)
            #pragma unroll
            for (int nf = 0; nf < 4; nf++) { hacc[mf][nf][0] = 0u; hacc[mf][nf][1] = 0u; }

        const uint32_t sa = sbase + bufb;
        const uint32_t sbm = sa + ATILE;
        #pragma unroll
        for (int kk = 0; kk < 4; kk++) {
            uint32_t af[2][4], bf[2][4];
            #pragma unroll
            for (int mf = 0; mf < 2; mf++)
                LDSM4(af[mf], sa + a_lm + mf * (16 * ROWB) + kk * 32);
            #pragma unroll
            for (int nf = 0; nf < 2; nf++)
                LDSM4(bf[nf], sbm + b_lm + nf * (16 * ROWB) + kk * 32);
            #pragma unroll
            for (int mf = 0; mf < 2; mf++)
                #pragma unroll
                for (int nfr = 0; nfr < 4; nfr++)
                    MMAH(hacc[mf][nfr], af[mf], bf[nfr >> 1][(nfr & 1) * 2], bf[nfr >> 1][(nfr & 1) * 2 + 1]);
        }
        __syncthreads();

        // ---- promote f16 stage partials to f32 accumulators ----
        #pragma unroll
        for (int mf = 0; mf < 2; mf++)
            #pragma unroll
            for (int nf = 0; nf < 4; nf++) {
                float2 f0 = __half22float2(*reinterpret_cast<__half2*>(&hacc[mf][nf][0]));
                float2 f1 = __half22float2(*reinterpret_cast<__half2*>(&hacc[mf][nf][1]));
                d[mf][nf][0] += f0.x;
                d[mf][nf][1] += f0.y;
                d[mf][nf][2] += f1.x;
                d[mf][nf][3] += f1.y;
            }
    }

    // ---- fused epilogue: out = dinv[m]*acc + bias[c] ----
    const int g = lane >> 2, tg = lane & 3;
    #pragma unroll
    for (int mf = 0; mf < 2; mf++) {
        #pragma unroll
        for (int nf = 0; nf < 4; nf++) {
            int m = m0 + wm * 32 + mf * 16 + g;
            int n = wn * 32 + nf * 8 + tg * 2;
            float di0 = __ldg(&dinv[m]);
            float di1 = __ldg(&dinv[m + 8]);
            float b0 = __ldg(&bias[n]), b1 = __ldg(&bias[n + 1]);
            float* o = out + (size_t)m * DFEAT + n;
            *reinterpret_cast<float2*>(o) =
                make_float2(d[mf][nf][0] * di0 + b0, d[mf][nf][1] * di0 + b1);
            *reinterpret_cast<float2*>(o + 8 * DFEAT) =
                make_float2(d[mf][nf][2] * di1 + b0, d[mf][nf][3] * di1 + b1);
        }
    }
}

// ---------------------------------------------------------------------------
// kernel_launch: inputs per metadata order: x, adj, W, b
// ---------------------------------------------------------------------------
extern "C" void kernel_launch(void* const* d_in, const int* in_sizes, int n_in,
                              void* d_out, int out_size) {
    const float* x   = (const float*)d_in[0];
    const float* adj = (const float*)d_in[1];
    const float* W   = (const float*)d_in[2];
    const float* b   = (const float*)d_in[3];
    float* out = (float*)d_out;

    float* dinv; cudaGetSymbolAddress((void**)&dinv, g_dinv);
    __half* zT;  cudaGetSymbolAddress((void**)&zT, g_zT);

    cudaFuncSetAttribute(gcn_mma_kernel, cudaFuncAttributeMaxDynamicSharedMemorySize, SMEM_DYN);

    rowsum_kernel<<<N_NODES, 256>>>(adj, dinv);
    xw_kernel<<<N_NODES / 8, 256>>>(x, W, dinv, zT);
    gcn_mma_kernel<<<N_NODES / BM, 256, SMEM_DYN>>>(adj, zT, dinv, b, out);
}

// round 11
// speedup vs baseline: 1.1653x; 1.1653x over previous
#include <cuda_runtime.h>
#include <cuda_fp16.h>
#include <cstdint>

// ---------------- problem constants ----------------
#define N_NODES 8192
#define DFEAT   128
#define EPS     1e-6f

// ---------------- GEMM tiling ----------------
#define KSPLIT   2
#define KHALF    (N_NODES / KSPLIT)     // 4096
#define BM       128
#define KSTAGE   64
#define NSTAGES  (KHALF / KSTAGE)       // 64
#define ROWB     144                    // smem row stride bytes (64 fp16 = 128B + 16 pad)
#define ATILE    (BM * ROWB)            // 18432
#define BTILE    (DFEAT * ROWB)         // 18432
#define BUFB     (ATILE + BTILE)        // 36864
#define SMEM_DYN (2 * BUFB)             // 73728

// ---------------- scratch (no allocation allowed) ----------------
__device__ float                   g_dinv[N_NODES];
__device__ __align__(16) __half    g_zT[DFEAT * N_NODES];           // [c][k] fp16
__device__ __align__(16) float     g_part[KSPLIT][N_NODES * DFEAT]; // 8 MB

// ---------------- helpers ----------------
static __device__ __forceinline__ uint32_t smem_u32(const void* p) {
    uint32_t a;
    asm("{ .reg .u64 t; cvta.to.shared.u64 t, %1; cvt.u32.u64 %0, t; }" : "=r"(a) : "l"(p));
    return a;
}

#define LDSM4(r, addr) \
    asm volatile("ldmatrix.sync.aligned.m8n8.x4.shared.b16 {%0,%1,%2,%3}, [%4];" \
        : "=r"((r)[0]), "=r"((r)[1]), "=r"((r)[2]), "=r"((r)[3]) : "r"(addr))

#define MMAF16(d, a, b0, b1) \
    asm volatile("mma.sync.aligned.m16n8k16.row.col.f32.f16.f16.f32 " \
        "{%0,%1,%2,%3}, {%4,%5,%6,%7}, {%8,%9}, {%0,%1,%2,%3};" \
        : "+f"((d)[0]), "+f"((d)[1]), "+f"((d)[2]), "+f"((d)[3]) \
        : "r"((a)[0]), "r"((a)[1]), "r"((a)[2]), "r"((a)[3]), "r"(b0), "r"(b1))

#define CPASYNC16(dst, src) \
    asm volatile("cp.async.cg.shared.global [%0], [%1], 16;" :: "r"(dst), "l"(src))
#define CP_COMMIT() asm volatile("cp.async.commit_group;" ::: "memory")
#define CP_WAIT1()  asm volatile("cp.async.wait_group 1;" ::: "memory")

static __device__ __forceinline__ uint2 f4_to_h4(float4 v) {
    __half2 p0 = __float22half2_rn(make_float2(v.x, v.y));
    __half2 p1 = __float22half2_rn(make_float2(v.z, v.w));
    uint2 r;
    r.x = *reinterpret_cast<uint32_t*>(&p0);
    r.y = *reinterpret_cast<uint32_t*>(&p1);
    return r;
}

// ---------------------------------------------------------------------------
// Kernel 1: dinv[i] = rsqrt(rowsum(adj_i) + eps)
// ---------------------------------------------------------------------------
__global__ void rowsum_kernel(const float* __restrict__ adj, float* __restrict__ dinv) {
    int row = blockIdx.x;
    const float4* p = reinterpret_cast<const float4*>(adj + (size_t)row * N_NODES);
    float s = 0.f;
    for (int j = threadIdx.x; j < N_NODES / 4; j += 256) {
        float4 v = p[j];
        s += (v.x + v.y) + (v.z + v.w);
    }
    #pragma unroll
    for (int off = 16; off > 0; off >>= 1) s += __shfl_down_sync(0xffffffffu, s, off);
    __shared__ float ws[8];
    int lane = threadIdx.x & 31, wid = threadIdx.x >> 5;
    if (lane == 0) ws[wid] = s;
    __syncthreads();
    if (wid == 0) {
        float t = (lane < 8) ? ws[lane] : 0.f;
        #pragma unroll
        for (int off = 4; off > 0; off >>= 1) t += __shfl_down_sync(0xffffffffu, t, off);
        if (lane == 0) dinv[row] = rsqrtf(t + EPS);
    }
}

// ---------------------------------------------------------------------------
// Kernel 2: zT[c][k] = fp16( dinv[k] * dot(x[k,:], W[c,:]) )   (fp32 math)
// ---------------------------------------------------------------------------
__global__ __launch_bounds__(256) void xw_kernel(
    const float* __restrict__ x, const float* __restrict__ W, const float* __restrict__ dinv,
    __half* __restrict__ zT)
{
    __shared__ float xs[8][DFEAT];
    __shared__ float zs[DFEAT][8];
    int r0 = blockIdx.x * 8;
    int t = threadIdx.x;
    for (int i = t; i < 8 * DFEAT; i += 256)
        xs[i >> 7][i & 127] = x[(size_t)r0 * DFEAT + i];
    __syncthreads();

    int c = t & 127, rh = t >> 7;
    const float4* wr = reinterpret_cast<const float4*>(W + (size_t)c * DFEAT);
    float acc[4] = {0.f, 0.f, 0.f, 0.f};
    #pragma unroll 8
    for (int k4 = 0; k4 < DFEAT / 4; k4++) {
        float4 wv = __ldg(&wr[k4]);
        #pragma unroll
        for (int j = 0; j < 4; j++) {
            const float* xr = &xs[rh * 4 + j][k4 * 4];
            acc[j] += wv.x * xr[0] + wv.y * xr[1] + wv.z * xr[2] + wv.w * xr[3];
        }
    }
    #pragma unroll
    for (int j = 0; j < 4; j++)
        zs[c][rh * 4 + j] = acc[j] * dinv[r0 + rh * 4 + j];
    __syncthreads();

    if (t < 128) {
        uint2 h0 = f4_to_h4(make_float4(zs[t][0], zs[t][1], zs[t][2], zs[t][3]));
        uint2 h1 = f4_to_h4(make_float4(zs[t][4], zs[t][5], zs[t][6], zs[t][7]));
        *reinterpret_cast<uint4*>(zT + (size_t)t * N_NODES + r0) = make_uint4(h0.x, h0.y, h1.x, h1.y);
    }
}

// ---------------------------------------------------------------------------
// Kernel 3: single-term fp16 GEMM (f32 acc) via mma.sync m16n8k16.
// part[kz][m][c] = sum_{k in half kz} adj[m][k] * z[k][c]
// Grid: 64 M-tiles x 2 K-halves = 128 CTAs. 512 threads = 16 warps (4/SMSP),
// warp grid 4(m) x 4(n), warp tile 32x32. Double-buffered smem, KSTAGE=64.
// B tiles via cp.async; A via LDG -> cvt fp16 -> STS.
// ---------------------------------------------------------------------------
__global__ __launch_bounds__(512, 1) void gcn_mma_kernel(
    const float* __restrict__ adj,
    const __half* __restrict__ zT,
    float* __restrict__ part)
{
    extern __shared__ char smem[];
    const uint32_t sbase = smem_u32(smem);

    const int tid  = threadIdx.x;
    const int lane = tid & 31;
    const int wid  = tid >> 5;
    const int wm   = wid >> 2;          // 0..3
    const int wn   = wid & 3;           // 0..3

    const int mt = blockIdx.x >> 1;
    const int kz = blockIdx.x & 1;
    const int m0 = mt * BM;
    const int kbase = kz * KHALF;
    float* pout = part + (size_t)kz * (N_NODES * DFEAT);

    // ---- global load mapping (fully coalesced) ----
    // A: 128 rows x 64 floats = 2048 float4; 4 per thread. row = (tid>>4) + i*32
    const float* aBase = adj + (size_t)(m0 + (tid >> 4)) * N_NODES + kbase + ((tid & 15) << 2);
    const uint32_t aSoff = (uint32_t)((tid >> 4) * ROWB + (tid & 15) * 8);
    // B: 128 n-rows x 64 halves = 1024 uint4; 2 per thread. n = (tid>>3) + i*64
    const __half* bBase = zT + (size_t)(tid >> 3) * N_NODES + kbase + ((tid & 7) << 3);
    const uint32_t bSoff = (uint32_t)((tid >> 3) * ROWB + (tid & 7) * 16);

    // ---- ldmatrix address precompute (verified round-3 mapping) ----
    const int idx = lane >> 3;   // 0..3
    const uint32_t a_lm = (uint32_t)((wm * 32 + (idx & 1) * 8 + (lane & 7)) * ROWB + ((idx >> 1) * 8) * 2);
    const uint32_t b_lm = (uint32_t)((wn * 32 + (idx >> 1) * 8 + (lane & 7)) * ROWB + ((idx & 1) * 8) * 2);

    float d[2][4][4];
    #pragma unroll
    for (int i = 0; i < 2; i++)
        #pragma unroll
        for (int j = 0; j < 4; j++)
            #pragma unroll
            for (int q = 0; q < 4; q++) d[i][j][q] = 0.f;

    // ---- prologue: issue B(0) cp.async into buf0, prefetch A(0) regs ----
    {
        uint32_t bdst = sbase + ATILE + bSoff;
        CPASYNC16(bdst, bBase);
        CPASYNC16(bdst + 64 * ROWB, bBase + (size_t)64 * N_NODES);
        CP_COMMIT();
    }
    float4 aP[4];
    #pragma unroll
    for (int i = 0; i < 4; i++)
        aP[i] = *reinterpret_cast<const float4*>(aBase + (size_t)(i * 32) * N_NODES);

    for (int s = 0; s < NSTAGES; s++) {
        const uint32_t bufb = (uint32_t)((s & 1) * BUFB);
        char* cbuf = smem + bufb;

        // ---- store A(s) regs -> smem (fp32 -> fp16) ----
        #pragma unroll
        for (int i = 0; i < 4; i++)
            *reinterpret_cast<uint2*>(cbuf + aSoff + i * (32 * ROWB)) = f4_to_h4(aP[i]);

        // ---- issue B(s+1) into other buffer; always commit (uniform group count) ----
        if (s + 1 < NSTAGES) {
            const int ko = (s + 1) * KSTAGE;
            uint32_t bdst = sbase + ((s + 1) & 1) * BUFB + ATILE + bSoff;
            CPASYNC16(bdst, bBase + ko);
            CPASYNC16(bdst + 64 * ROWB, bBase + (size_t)64 * N_NODES + ko);
        }
        CP_COMMIT();

        // ---- prefetch A(s+1) regs ----
        if (s + 1 < NSTAGES) {
            const int ko = (s + 1) * KSTAGE;
            #pragma unroll
            for (int i = 0; i < 4; i++)
                aP[i] = *reinterpret_cast<const float4*>(aBase + (size_t)(i * 32) * N_NODES + ko);
        }

        // ---- wait for B(s), sync, MMA ----
        CP_WAIT1();
        __syncthreads();

        const uint32_t sa = sbase + bufb;
        const uint32_t sbm = sa + ATILE;
        #pragma unroll
        for (int kk = 0; kk < 4; kk++) {
            uint32_t af[2][4], bf[2][4];
            #pragma unroll
            for (int mf = 0; mf < 2; mf++)
                LDSM4(af[mf], sa + a_lm + mf * (16 * ROWB) + kk * 32);
            #pragma unroll
            for (int nf = 0; nf < 2; nf++)
                LDSM4(bf[nf], sbm + b_lm + nf * (16 * ROWB) + kk * 32);
            #pragma unroll
            for (int mf = 0; mf < 2; mf++)
                #pragma unroll
                for (int nfr = 0; nfr < 4; nfr++)
                    MMAF16(d[mf][nfr], af[mf], bf[nfr >> 1][(nfr & 1) * 2], bf[nfr >> 1][(nfr & 1) * 2 + 1]);
        }
        __syncthreads();
    }

    // ---- epilogue: write partials ----
    const int g = lane >> 2, tg = lane & 3;
    #pragma unroll
    for (int mf = 0; mf < 2; mf++) {
        #pragma unroll
        for (int nf = 0; nf < 4; nf++) {
            int m = m0 + wm * 32 + mf * 16 + g;
            int n = wn * 32 + nf * 8 + tg * 2;
            float* o = pout + (size_t)m * DFEAT + n;
            *reinterpret_cast<float2*>(o) = make_float2(d[mf][nf][0], d[mf][nf][1]);
            *reinterpret_cast<float2*>(o + 8 * DFEAT) = make_float2(d[mf][nf][2], d[mf][nf][3]);
        }
    }
}

// ---------------------------------------------------------------------------
// Kernel 4: out[m][c] = dinv[m] * (p0 + p1)[m][c] + b[c]
// ---------------------------------------------------------------------------
__global__ void reduce_kernel(const float* __restrict__ p0, const float* __restrict__ p1,
                              const float* __restrict__ dinv, const float* __restrict__ bias,
                              float* __restrict__ out)
{
    int idx = blockIdx.x * blockDim.x + threadIdx.x;
    int e = idx << 2;
    int m = e >> 7, c = e & 127;
    float4 a = reinterpret_cast<const float4*>(p0)[idx];
    float4 b = reinterpret_cast<const float4*>(p1)[idx];
    float di = __ldg(&dinv[m]);
    float4 bb = *reinterpret_cast<const float4*>(bias + c);
    float4 o;
    o.x = di * (a.x + b.x) + bb.x;
    o.y = di * (a.y + b.y) + bb.y;
    o.z = di * (a.z + b.z) + bb.z;
    o.w = di * (a.w + b.w) + bb.w;
    reinterpret_cast<float4*>(out)[idx] = o;
}

// ---------------------------------------------------------------------------
// kernel_launch: inputs per metadata order: x, adj, W, b
// ---------------------------------------------------------------------------
extern "C" void kernel_launch(void* const* d_in, const int* in_sizes, int n_in,
                              void* d_out, int out_size) {
    const float* x   = (const float*)d_in[0];
    const float* adj = (const float*)d_in[1];
    const float* W   = (const float*)d_in[2];
    const float* b   = (const float*)d_in[3];
    float* out = (float*)d_out;

    float* dinv; cudaGetSymbolAddress((void**)&dinv, g_dinv);
    __half* zT;  cudaGetSymbolAddress((void**)&zT, g_zT);
    float* part; cudaGetSymbolAddress((void**)&part, g_part);

    cudaFuncSetAttribute(gcn_mma_kernel, cudaFuncAttributeMaxDynamicSharedMemorySize, SMEM_DYN);

    rowsum_kernel<<<N_NODES, 256>>>(adj, dinv);
    xw_kernel<<<N_NODES / 8, 256>>>(x, W, dinv, zT);
    gcn_mma_kernel<<<(N_NODES / BM) * KSPLIT, 512, SMEM_DYN>>>(adj, zT, part);
    reduce_kernel<<<(N_NODES * DFEAT / 4) / 256, 256>>>(part, part + (size_t)N_NODES * DFEAT,
                                                        dinv, b, out);
}